// round 16
// baseline (speedup 1.0000x reference)
#include <cuda_runtime.h>
#include <cuda_fp16.h>
#include <cstdint>

#define B_    16
#define C_    256
#define WIN   4096
#define OC_   256
#define KT    3
#define WOUT  4096
#define KTOT  768            // kk = k*256 + c
#define NCHUNK 24            // physical K chunks of 32 (mma.sync path)
#define ROWB  80             // smem row stride bytes (32 fp16 + pad, conflict-free)
#define TILE_BYTES (128 * ROWB)          // 10240
#define STG_BYTES  (2 * TILE_BYTES)      // A + B = 20480
#define NSTAGE 4
#define SMEM_BYTES (NSTAGE * STG_BYTES)  // 81920

#if defined(__CUDA_ARCH_FEAT_SM103_ALL) || defined(__CUDA_ARCH_FEAT_SM100_ALL)
#define HAS_TCGEN05 1
#else
#define HAS_TCGEN05 0
#endif

// ---------------- scratch (static device globals; no allocation) ----------------
__device__ __align__(16) __half g_xth[(size_t)B_ * WIN * C_];     // [b][i][c] fp16
__device__ __align__(16) __half g_sh [(size_t)B_ * WOUT * KTOT];  // [b][w][kk] fp16 samples
__device__ __align__(16) __half g_wh [OC_ * KTOT];                // [oc][kk]   fp16 weights
__device__ __align__(16) float  g_probe[OC_ * 128];               // tcgen05 probe scratch

// ---------------- helpers ----------------
__device__ __forceinline__ uint32_t smem_u32(const void* p) {
    uint32_t a;
    asm("{ .reg .u64 t; cvta.to.shared.u64 t, %1; cvt.u32.u64 %0, t; }" : "=r"(a) : "l"(p));
    return a;
}
__device__ __forceinline__ uint32_t h2_u32(__half2 h) {
    return *reinterpret_cast<uint32_t*>(&h);
}
__device__ __forceinline__ void cpa16(uint32_t dst, const void* src) {
    asm volatile("cp.async.cg.shared.global [%0], [%1], 16;" :: "r"(dst), "l"(src));
}
#define SWZ(o) ((o) ^ (((o) >> 3) & 0x70))
__device__ __forceinline__ void ldsm4(uint32_t& r0, uint32_t& r1, uint32_t& r2, uint32_t& r3,
                                      uint32_t addr) {
    asm volatile("ldmatrix.sync.aligned.m8n8.x4.shared.b16 {%0,%1,%2,%3}, [%4];"
                 : "=r"(r0), "=r"(r1), "=r"(r2), "=r"(r3) : "r"(addr));
}
__device__ __forceinline__ void mma16816(float* d, const uint32_t* a, const uint32_t* b) {
    asm volatile(
        "mma.sync.aligned.m16n8k16.row.col.f32.f16.f16.f32 "
        "{%0,%1,%2,%3}, {%4,%5,%6,%7}, {%8,%9}, {%0,%1,%2,%3};"
        : "+f"(d[0]), "+f"(d[1]), "+f"(d[2]), "+f"(d[3])
        : "r"(a[0]), "r"(a[1]), "r"(a[2]), "r"(a[3]), "r"(b[0]), "r"(b[1]));
}
__device__ __forceinline__ uint32_t elect1() {
    uint32_t r;
    asm volatile("{ .reg .pred p; elect.sync _|p, 0xFFFFFFFF; selp.b32 %0, 1, 0, p; }" : "=r"(r));
    return r;
}
__device__ __forceinline__ uint64_t mkdesc(uint32_t addr) {
    const uint64_t base = (2ull << 61) | (1ull << 46) | (64ull << 32) | (1ull << 16);
    return base | ((uint64_t)(addr >> 4) & 0x3FFF);
}
#define IDESC_F16 ((1u << 4) | (16u << 17) | (8u << 24))   // f16xf16->f32, M=128, N=128

__device__ __forceinline__ void mbar_init(uint32_t a, uint32_t cnt) {
    asm volatile("mbarrier.init.shared.b64 [%0], %1;" :: "r"(a), "r"(cnt) : "memory");
}
__device__ __forceinline__ void mbar_wait(uint32_t a, uint32_t parity) {
    uint32_t done;
    asm volatile(
        "{\n\t.reg .pred p;\n\t"
        "mbarrier.try_wait.parity.acquire.cta.shared::cta.b64 p, [%1], %2;\n\t"
        "selp.b32 %0, 1, 0, p;\n\t}"
        : "=r"(done) : "r"(a), "r"(parity) : "memory");
    if (!done) {
        asm volatile(
            "{\n\t.reg .pred P1;\n\t"
            "WAIT_LOOP_%=:\n\t"
            "mbarrier.try_wait.parity.acquire.cta.shared::cta.b64 P1, [%0], %1, 0x989680;\n\t"
            "@P1 bra.uni WAIT_DONE_%=;\n\t"
            "bra.uni WAIT_LOOP_%=;\n\t"
            "WAIT_DONE_%=:\n\t}"
            :: "r"(a), "r"(parity) : "memory");
    }
}

#if HAS_TCGEN05
__device__ __forceinline__ void mma_f16(uint32_t d, uint64_t ad, uint64_t bd, uint32_t en) {
    asm volatile(
        "{\n\t.reg .pred p;\n\tsetp.ne.u32 p, %4, 0;\n\t"
        "tcgen05.mma.cta_group::1.kind::f16 [%0], %1, %2, %3, {%5, %5, %5, %5}, p;\n\t}"
        :: "r"(d), "l"(ad), "l"(bd), "r"(IDESC_F16), "r"(en), "r"(0u) : "memory");
}
__device__ __forceinline__ void ldtm_x32(uint32_t* r, uint32_t addr) {
    asm volatile(
        "tcgen05.ld.sync.aligned.32x32b.x32.b32 "
        "{%0, %1, %2, %3, %4, %5, %6, %7, "
        " %8, %9, %10, %11, %12, %13, %14, %15, "
        " %16, %17, %18, %19, %20, %21, %22, %23, "
        " %24, %25, %26, %27, %28, %29, %30, %31}, [%32];"
        : "=r"(r[0]), "=r"(r[1]), "=r"(r[2]), "=r"(r[3]),
          "=r"(r[4]), "=r"(r[5]), "=r"(r[6]), "=r"(r[7]),
          "=r"(r[8]), "=r"(r[9]), "=r"(r[10]), "=r"(r[11]),
          "=r"(r[12]), "=r"(r[13]), "=r"(r[14]), "=r"(r[15]),
          "=r"(r[16]), "=r"(r[17]), "=r"(r[18]), "=r"(r[19]),
          "=r"(r[20]), "=r"(r[21]), "=r"(r[22]), "=r"(r[23]),
          "=r"(r[24]), "=r"(r[25]), "=r"(r[26]), "=r"(r[27]),
          "=r"(r[28]), "=r"(r[29]), "=r"(r[30]), "=r"(r[31])
        : "r"(addr));
}
#endif

// ---------------- kernel 1: transpose x[b][c][i] -> xth[b][i][c] (fp16) ------------
__global__ void transpose_x(const float* __restrict__ x) {
    __shared__ float tile[32][33];
    int b = blockIdx.z;
    int i0 = blockIdx.x * 32, c0 = blockIdx.y * 32;
    int tx = threadIdx.x, ty = threadIdx.y;            // 32 x 8
    const float* xb = x + (size_t)b * C_ * WIN;
    #pragma unroll
    for (int r = 0; r < 32; r += 8)
        tile[ty + r][tx] = xb[(size_t)(c0 + ty + r) * WIN + i0 + tx];
    __syncthreads();
    __half* xtb = g_xth + (size_t)b * WIN * C_;
    #pragma unroll
    for (int r = 0; r < 32; r += 8)
        xtb[(size_t)(i0 + ty + r) * C_ + c0 + tx] = __float2half(tile[tx][ty + r]);
}

// ---------------- kernel 2: weight -> fp16, kk-major ----------------
__global__ void prep_weight(const float* __restrict__ weight) {
    int t = blockIdx.x * 256 + threadIdx.x;            // t = oc*768 + kk
    if (t >= OC_ * KTOT) return;
    int oc = t / KTOT, kk = t - oc * KTOT;
    int k = kk >> 8, c = kk & 255;
    g_wh[t] = __float2half(weight[oc * KTOT + c * KT + k]);
}

// ---------------- kernel 3: modulated bilinear sampling (fp16 in, fp16 out) --------
__global__ __launch_bounds__(256)
void sample_kernel(const float* __restrict__ offset, const float* __restrict__ mask) {
    int gw   = blockIdx.x * 8 + (threadIdx.x >> 5);    // one warp per (b,w)
    int lane = threadIdx.x & 31;
    int b = gw >> 12;
    int w = gw & 4095;
    const __half* xtb = g_xth + (size_t)b * WIN * C_;
    size_t srow = ((size_t)b * WOUT + w) * KTOT;
    #pragma unroll
    for (int k = 0; k < KT; k++) {
        float off = offset[((size_t)b * KT + k) * WOUT + w];
        float m   = mask  [((size_t)b * KT + k) * WOUT + w];
        float p  = (float)(w - 1 + k) + off;           // stride=1, pad=1, dil=1
        float pf = floorf(p);
        int   i0 = (int)pf;
        float fr = p - pf;
        int   i1 = i0 + 1;
        float c0 = (1.0f - fr) * m;
        float c1 = fr * m;
        if (i0 < 0 || i0 >= WIN) { i0 = 0; c0 = 0.0f; }
        if (i1 < 0 || i1 >= WIN) { i1 = 0; c1 = 0.0f; }
        uint4 q0 = ((const uint4*)(xtb + (size_t)i0 * C_))[lane];
        uint4 q1 = ((const uint4*)(xtb + (size_t)i1 * C_))[lane];
        const __half2* a2 = (const __half2*)&q0;
        const __half2* b2 = (const __half2*)&q1;
        uint32_t o[4];
        #pragma unroll
        for (int j = 0; j < 4; j++) {
            float2 f = __half22float2(a2[j]);
            float2 g = __half22float2(b2[j]);
            o[j] = h2_u32(__floats2half2_rn(c0 * f.x + c1 * g.x,
                                            c0 * f.y + c1 * g.y));
        }
        *(uint4*)(g_sh + srow + k * 256 + lane * 8) = make_uint4(o[0], o[1], o[2], o[3]);
    }
}

// ---------------- kernel 4: GEMM via mma.sync fp16 (R14, grid-swapped) ------------
__global__ __launch_bounds__(256, 2)
void gemm_kernel(const float* __restrict__ bias, float* __restrict__ out) {
    extern __shared__ char smem[];
    uint32_t sbase = smem_u32(smem);
    int tid = threadIdx.x, lane = tid & 31, wid = tid >> 5;
    int wm = wid & 1, wn = wid >> 1;                   // warp grid 2 (m) x 4 (n)
    int mt = blockIdx.x, nt = blockIdx.y, bz = blockIdx.z;  // x fastest -> B-tile reuse
    int mbase = mt * 128, nbase = nt * 128;

    float acc[4][4][4];
    #pragma unroll
    for (int i = 0; i < 4; i++)
        #pragma unroll
        for (int j = 0; j < 4; j++)
            #pragma unroll
            for (int q = 0; q < 4; q++) acc[i][j][q] = 0.0f;

    auto issue = [&](int pc) {
        int kk0 = pc * 32;
        uint32_t st = sbase + (uint32_t)(pc & (NSTAGE - 1)) * STG_BYTES;
        #pragma unroll
        for (int r = 0; r < 2; r++) {
            int id = tid + r * 256;                    // 0..511
            int row = id >> 2, seg = id & 3;           // 128 rows x 4 x 16B
            uint32_t off = (uint32_t)(row * ROWB + seg * 16);
            cpa16(st + off,
                  g_wh + (size_t)(mbase + row) * KTOT + kk0 + seg * 8);
            cpa16(st + TILE_BYTES + off,
                  g_sh + ((size_t)bz * WOUT + nbase + row) * KTOT + kk0 + seg * 8);
        }
        asm volatile("cp.async.commit_group;" ::: "memory");
    };

    issue(0); issue(1); issue(2);

    int arow = (lane & 7) + ((lane >> 3) & 1) * 8;
    int acol = ((lane >> 4) & 1) * 8;
    int brow8 = ((lane >> 4) & 1) * 8 + (lane & 7);
    int bcol  = ((lane >> 3) & 1) * 8;

    for (int pc = 0; pc < NCHUNK; pc++) {
        asm volatile("cp.async.wait_group 2;" ::: "memory");
        __syncthreads();

        uint32_t st = sbase + (uint32_t)(pc & (NSTAGE - 1)) * STG_BYTES;
        uint32_t sA = st, sB = st + TILE_BYTES;

        #pragma unroll
        for (int ko = 0; ko < 32; ko += 16) {
            uint32_t bf[4][2];
            #pragma unroll
            for (int jj = 0; jj < 4; jj += 2) {
                uint32_t boff = (uint32_t)((wn * 32 + jj * 8 + brow8) * ROWB
                                           + (ko + bcol) * 2);
                ldsm4(bf[jj][0], bf[jj][1], bf[jj + 1][0], bf[jj + 1][1], sB + boff);
            }
            #pragma unroll
            for (int i = 0; i < 4; i++) {
                uint32_t aoff = (uint32_t)((wm * 64 + i * 16 + arow) * ROWB
                                           + (ko + acol) * 2);
                uint32_t a[4];
                ldsm4(a[0], a[1], a[2], a[3], sA + aoff);
                #pragma unroll
                for (int j = 0; j < 4; j++)
                    mma16816(acc[i][j], a, bf[j]);
            }
        }
        __syncthreads();

        if (pc + 3 < NCHUNK) issue(pc + 3);
    }

    int r4 = lane >> 2, c2 = (lane & 3) * 2;
    #pragma unroll
    for (int i = 0; i < 4; i++) {
        int oc0 = mbase + wm * 64 + i * 16 + r4;
        float bs0 = bias[oc0];
        float bs1 = bias[oc0 + 8];
        #pragma unroll
        for (int j = 0; j < 4; j++) {
            int w = nbase + wn * 32 + j * 8 + c2;
            float2 v0, v1;
            v0.x = acc[i][j][0] + bs0; v0.y = acc[i][j][1] + bs0;
            v1.x = acc[i][j][2] + bs1; v1.y = acc[i][j][3] + bs1;
            *(float2*)&out[((size_t)(bz * OC_ + oc0)) * WOUT + w]     = v0;
            *(float2*)&out[((size_t)(bz * OC_ + oc0 + 8)) * WOUT + w] = v1;
        }
    }
}

// ---------------- kernel 5: tcgen05 PROBE (1 CTA, single chunk, writes scratch) ----
// Bisect: exercises alloc/cpa16+SWZ/fence/elect MMA x8/commit/mbar/ldtm/dealloc.
#define P_A_BYTES 32768u
#define P_B_BYTES 16384u
#define PROBE_SMEM (1024 + 1024 + P_A_BYTES + P_B_BYTES)   // 51200

__global__ __launch_bounds__(256, 1) __cluster_dims__(1, 1, 1)
void probe_kernel() {
#if HAS_TCGEN05
    extern __shared__ char smem[];
    int tid = threadIdx.x, lane = tid & 31, wid = tid >> 5;
    uint32_t sraw  = smem_u32(smem);
    uint32_t sbase = (sraw + 1023u) & ~1023u;
    uint32_t mbar  = sbase + 8;
    uint32_t stg   = sbase + 1024;

    if (wid == 0) {
        asm volatile("tcgen05.alloc.cta_group::1.sync.aligned.shared::cta.b32 [%0], %1;"
                     :: "r"(sbase), "r"(512u) : "memory");
    } else {
        asm volatile("tcgen05.relinquish_alloc_permit.cta_group::1.sync.aligned;");
    }
    if (tid == 0) mbar_init(mbar, 1);
    __syncthreads();
    uint32_t tmem;
    asm volatile("ld.shared.b32 %0, [%1];" : "=r"(tmem) : "r"(sbase) : "memory");

    // fill: A = g_wh chunk0 (256 x 64 fp16), B = g_sh b=0 w=0..127 chunk0
    #pragma unroll
    for (int t = 0; t < 8; t++) {
        int id = tid + t * 256;
        int row = id >> 3, sg = id & 7;
        cpa16(stg + SWZ((uint32_t)(row * 128 + sg * 16)),
              g_wh + (size_t)row * KTOT + sg * 8);
    }
    #pragma unroll
    for (int t = 0; t < 4; t++) {
        int id = tid + t * 256;
        int row = id >> 3, sg = id & 7;
        cpa16(stg + P_A_BYTES + SWZ((uint32_t)(row * 128 + sg * 16)),
              g_sh + (size_t)row * KTOT + sg * 8);
    }
    asm volatile("cp.async.commit_group;" ::: "memory");
    asm volatile("cp.async.wait_group 0;" ::: "memory");
    __syncthreads();
    asm volatile("fence.proxy.async.shared::cta;" ::: "memory");

    if (wid == 0 && elect1()) {
        uint64_t dA = mkdesc(stg);
        uint64_t dB = mkdesc(stg + P_A_BYTES);
        #pragma unroll
        for (int half = 0; half < 2; half++) {
            #pragma unroll
            for (int ks = 0; ks < 4; ks++) {
                uint32_t en = (ks == 0) ? 0u : 1u;     // per-half first MMA inits
                mma_f16(tmem + half * 128, dA + half * 1024 + ks * 2, dB + ks * 2, en);
            }
        }
        asm volatile(
            "tcgen05.commit.cta_group::1.mbarrier::arrive::one.shared::cluster.b64 [%0];"
            :: "r"(mbar) : "memory");
    }
    mbar_wait(mbar, 0);
    asm volatile("tcgen05.fence::after_thread_sync;" ::: "memory");

    int half = wid >> 2, sp = wid & 3;
    int oc = half * 128 + sp * 32 + lane;
    float* op = g_probe + (size_t)oc * 128;
    #pragma unroll
    for (int cc = 0; cc < 4; cc++) {
        uint32_t r[32];
        ldtm_x32(r, tmem + half * 128 + cc * 32);
        asm volatile("tcgen05.wait::ld.sync.aligned;" ::: "memory");
        #pragma unroll
        for (int j = 0; j < 8; j++) {
            float4 v;
            v.x = __uint_as_float(r[4 * j + 0]);
            v.y = __uint_as_float(r[4 * j + 1]);
            v.z = __uint_as_float(r[4 * j + 2]);
            v.w = __uint_as_float(r[4 * j + 3]);
            *(float4*)(op + cc * 32 + j * 4) = v;
        }
    }
    asm volatile("tcgen05.fence::before_thread_sync;" ::: "memory");
    __syncthreads();
    if (wid == 0) {
        asm volatile("tcgen05.dealloc.cta_group::1.sync.aligned.b32 %0, %1;"
                     :: "r"(tmem), "r"(512u));
    }
#endif
}

// ---------------- launch ----------------
extern "C" void kernel_launch(void* const* d_in, const int* in_sizes, int n_in,
                              void* d_out, int out_size) {
    const float* x      = (const float*)d_in[0];   // [16,256,4096]
    const float* weight = (const float*)d_in[1];   // [256,256,3]
    const float* offset = (const float*)d_in[2];   // [16,3,4096]
    const float* mask   = (const float*)d_in[3];   // [16,3,4096]
    const float* bias   = (const float*)d_in[4];   // [256]
    float* out = (float*)d_out;                    // [16,256,4096]

    cudaFuncSetAttribute(gemm_kernel, cudaFuncAttributeMaxDynamicSharedMemorySize,
                         SMEM_BYTES);
    cudaFuncSetAttribute(probe_kernel, cudaFuncAttributeMaxDynamicSharedMemorySize,
                         PROBE_SMEM);

    {
        dim3 grid(WIN / 32, C_ / 32, B_);
        transpose_x<<<grid, dim3(32, 8)>>>(x);
    }
    prep_weight<<<(OC_ * KTOT + 255) / 256, 256>>>(weight);
    sample_kernel<<<B_ * WOUT / 8, 256>>>(offset, mask);
    {
        dim3 grid(OC_ / 128, WOUT / 128, B_);      // 2 x 32 x 16 = 1024 CTAs
        gemm_kernel<<<grid, 256, SMEM_BYTES>>>(bias, out);
    }
    // tcgen05 bisect probe: result unused; pass/fail of the run is the signal
    probe_kernel<<<1, 256, PROBE_SMEM>>>();
}